// round 13
// baseline (speedup 1.0000x reference)
#include <cuda_runtime.h>
#include <cuda_bf16.h>
#include <float.h>

#define BATCH 8
#define NPTS  2048
#define KNN   20
#define EPSBN 1e-5f

// ---------------- scratch (device globals; no runtime allocation) ----------------
__device__ float g_xin3[BATCH * NPTS * 3];
__device__ float g_xcat[BATCH * NPTS * 512];
__device__ float g_sq[BATCH * NPTS];
__device__ float g_pd[(size_t)BATCH * NPTS * NPTS];
__device__ int   g_idx[BATCH * NPTS * KNN];
__device__ float g_wpack[512 * 256];
__device__ float g_aq[(size_t)BATCH * NPTS * 512];
__device__ float g_mx[(size_t)BATCH * NPTS * 256];
__device__ float g_mn[(size_t)BATCH * NPTS * 256];
__device__ float g_s1[256];
__device__ float g_s2[256];
__device__ float g_fmx[BATCH * 1024];
__device__ float g_fmn[BATCH * 1024];
__device__ float g_fs1[1024];
__device__ float g_fs2[1024];
// deterministic-reduction scratch (one slot per contributor; NO float atomics anywhere)
__device__ float g_ps1[256 * 4096];
__device__ float g_ps2[256 * 4096];
__device__ float g_pfs1[1024 * 128];
__device__ float g_pfs2[1024 * 128];
// head bf16 double-split operands
__device__ __nv_bfloat16 g_w5h[1024 * 512];
__device__ __nv_bfloat16 g_w5l[1024 * 512];
__device__ __nv_bfloat16 g_xch[(size_t)BATCH * NPTS * 512];
__device__ __nv_bfloat16 g_xcl[(size_t)BATCH * NPTS * 512];

// ---------------- helpers (max/min atomics are order-independent => deterministic) ----------------
__device__ __forceinline__ void atomicMaxFloat(float* a, float v) {
    if (v >= 0.f) atomicMax((int*)a, __float_as_int(v));
    else          atomicMin((unsigned int*)a, __float_as_uint(v));
}
__device__ __forceinline__ void atomicMinFloat(float* a, float v) {
    if (v >= 0.f) atomicMin((int*)a, __float_as_int(v));
    else          atomicMax((unsigned int*)a, __float_as_uint(v));
}

// ---------------- small kernels ----------------

__global__ void transpose_in_kernel(const float* __restrict__ x) {
    int id = blockIdx.x * blockDim.x + threadIdx.x;
    if (id >= BATCH * 3 * NPTS) return;
    int n = id % NPTS;
    int c = (id / NPTS) % 3;
    int b = id / (3 * NPTS);
    g_xin3[((size_t)(b * NPTS + n)) * 3 + c] = x[id];
}

__global__ void sq_kernel(int src, int coloff, int C, int S) {
    int row = blockIdx.x * 8 + (threadIdx.x >> 5);
    int lane = threadIdx.x & 31;
    const float* X = (src ? g_xcat : g_xin3) + (size_t)row * S + coloff;
    float s = 0.f;
    for (int c = lane; c < C; c += 32) s = fmaf(X[c], X[c], s);
#pragma unroll
    for (int off = 16; off; off >>= 1) s += __shfl_down_sync(0xffffffffu, s, off);
    if (lane == 0) g_sq[row] = s;
}

// ---------------- layer-1 gram v2: 32 n-rows per block, smem-staged m-chunks ----------------
// Value expression identical to the zero-padded tile (fmaf chain, 2*acc - sn - sm)
// => pd bit-identical. Block reads x/sq once per 256-m chunk; writes coalesced.
__global__ __launch_bounds__(256) void gram1_kernel() {
    __shared__ float sx[256 * 3];
    __shared__ float ssq[256];
    int bb = blockIdx.y;
    int n0 = blockIdx.x * 32;
    int tid = threadIdx.x, lane = tid & 31, w = tid >> 5;
    const float* Xb  = g_xin3 + (size_t)bb * NPTS * 3;
    const float* sqb = g_sq + bb * NPTS;

    float xn[4][3], sn[4];
#pragma unroll
    for (int r = 0; r < 4; r++) {
        int n = n0 + w * 4 + r;
        xn[r][0] = Xb[n * 3 + 0];
        xn[r][1] = Xb[n * 3 + 1];
        xn[r][2] = Xb[n * 3 + 2];
        sn[r] = sqb[n];
    }

    for (int mc = 0; mc < NPTS; mc += 256) {
        sx[tid]       = Xb[mc * 3 + tid];
        sx[256 + tid] = Xb[mc * 3 + 256 + tid];
        sx[512 + tid] = Xb[mc * 3 + 512 + tid];
        ssq[tid]      = sqb[mc + tid];
        __syncthreads();
#pragma unroll
        for (int r = 0; r < 4; r++) {
            int n = n0 + w * 4 + r;
            float* row = g_pd + ((size_t)bb * NPTS + n) * NPTS + mc;
            float x0 = xn[r][0], x1 = xn[r][1], x2 = xn[r][2], s = sn[r];
#pragma unroll
            for (int mm0 = 0; mm0 < 256; mm0 += 32) {
                int mm = mm0 + lane;
                float acc = 0.f;
                acc = fmaf(x0, sx[mm * 3 + 0], acc);
                acc = fmaf(x1, sx[mm * 3 + 1], acc);
                acc = fmaf(x2, sx[mm * 3 + 2], acc);
                row[mm] = 2.f * acc - s - ssq[mm];
            }
        }
        __syncthreads();
    }
}

// ---------------- 128x128x8 SGEMM mainloop, double-buffered (layers 2-4) ----------------

template<int KDIM, int ASTR, int BSTR>
__device__ __forceinline__ void gemm_mainloop(const float* __restrict__ A,
                                              const float* __restrict__ B,
                                              float (&As)[2][8][132], float (&Bs)[2][8][132],
                                              float (&acc)[8][8],
                                              int tid, int tx, int ty) {
    constexpr bool VEC = (KDIM % 8 == 0) && (ASTR % 4 == 0) && (BSTR % 4 == 0);
    constexpr int NT = (KDIM + 7) / 8;
    int ar = tid >> 1;
    int ac = (tid & 1) * 4;
    float ra[4], rb[4];

    if (VEC) {
        float4 a4 = *reinterpret_cast<const float4*>(A + (size_t)ar * ASTR + ac);
        float4 b4 = *reinterpret_cast<const float4*>(B + (size_t)ar * BSTR + ac);
        ra[0] = a4.x; ra[1] = a4.y; ra[2] = a4.z; ra[3] = a4.w;
        rb[0] = b4.x; rb[1] = b4.y; rb[2] = b4.z; rb[3] = b4.w;
    } else {
#pragma unroll
        for (int j = 0; j < 4; j++) {
            int gc = ac + j;
            ra[j] = (gc < KDIM) ? A[(size_t)ar * ASTR + gc] : 0.f;
            rb[j] = (gc < KDIM) ? B[(size_t)ar * BSTR + gc] : 0.f;
        }
    }
#pragma unroll
    for (int j = 0; j < 4; j++) { As[0][ac + j][ar] = ra[j]; Bs[0][ac + j][ar] = rb[j]; }
    __syncthreads();

    for (int t = 0; t < NT; t++) {
        if (t + 1 < NT) {
            int kk = (t + 1) * 8;
            if (VEC) {
                float4 a4 = *reinterpret_cast<const float4*>(A + (size_t)ar * ASTR + kk + ac);
                float4 b4 = *reinterpret_cast<const float4*>(B + (size_t)ar * BSTR + kk + ac);
                ra[0] = a4.x; ra[1] = a4.y; ra[2] = a4.z; ra[3] = a4.w;
                rb[0] = b4.x; rb[1] = b4.y; rb[2] = b4.z; rb[3] = b4.w;
            } else {
#pragma unroll
                for (int j = 0; j < 4; j++) {
                    int gc = kk + ac + j;
                    ra[j] = (gc < KDIM) ? A[(size_t)ar * ASTR + gc] : 0.f;
                    rb[j] = (gc < KDIM) ? B[(size_t)ar * BSTR + gc] : 0.f;
                }
            }
        }
        int cur = t & 1;
#pragma unroll
        for (int k = 0; k < 8; k++) {
            float a[8], b[8];
#pragma unroll
            for (int i = 0; i < 8; i++) a[i] = As[cur][k][ty * 8 + i];
#pragma unroll
            for (int i = 0; i < 8; i++) b[i] = Bs[cur][k][tx * 8 + i];
#pragma unroll
            for (int i = 0; i < 8; i++)
#pragma unroll
                for (int j = 0; j < 8; j++)
                    acc[i][j] = fmaf(a[i], b[j], acc[i][j]);
        }
        if (t + 1 < NT) {
            int nxt = (t + 1) & 1;
#pragma unroll
            for (int j = 0; j < 4; j++) { As[nxt][ac + j][ar] = ra[j]; Bs[nxt][ac + j][ar] = rb[j]; }
            __syncthreads();
        }
    }
}

// pd = 2*X Xt - sq_n - sq_m; triangle blocks; mirror written COALESCED via smem transpose.
template<int C, int S, int COLOFF>
__global__ __launch_bounds__(256, 2) void gram_kernel() {
    __shared__ float As[2][8][132];
    __shared__ float Bs[2][8][132];
    __shared__ float tbuf[16][136];
    int bb = blockIdx.z;
    int t = blockIdx.x, br = 0;
    while (t >= 16 - br) { t -= 16 - br; br++; }
    int bc = br + t;
    int nBase = br * 128, mBase = bc * 128;

    const float* Xb = g_xcat + (size_t)bb * NPTS * S + COLOFF;
    int tid = threadIdx.x;
    int tx = tid & 15, ty = tid >> 4;
    float acc[8][8] = {};

    gemm_mainloop<C, S, S>(Xb + (size_t)nBase * S, Xb + (size_t)mBase * S,
                           As, Bs, acc, tid, tx, ty);

    const float* sqb = g_sq + bb * NPTS;
    float* pdb = g_pd + (size_t)bb * NPTS * NPTS;

    float sn_r[8], sqm_r[8];
#pragma unroll
    for (int i = 0; i < 8; i++) sn_r[i] = sqb[nBase + ty * 8 + i];
#pragma unroll
    for (int j = 0; j < 8; j++) sqm_r[j] = sqb[mBase + tx * 8 + j];

#pragma unroll
    for (int i = 0; i < 8; i++) {
        int n = nBase + ty * 8 + i;
#pragma unroll
        for (int j = 0; j < 8; j++) {
            pdb[(size_t)n * NPTS + mBase + tx * 8 + j] = 2.f * acc[i][j] - sn_r[i] - sqm_r[j];
        }
    }

    if (br != bc) {
        for (int s = 0; s < 8; s++) {
            if ((tx >> 1) == s) {
#pragma unroll
                for (int i = 0; i < 8; i++)
#pragma unroll
                    for (int j = 0; j < 8; j++)
                        tbuf[(tx & 1) * 8 + j][ty * 8 + i] = 2.f * acc[i][j] - sn_r[i] - sqm_r[j];
            }
            __syncthreads();
            int rr = tid >> 4;
            int c0 = (tid & 15) * 8;
            float* dst = pdb + (size_t)(mBase + s * 16 + rr) * NPTS + nBase + c0;
            float4 v0 = *reinterpret_cast<float4*>(&tbuf[rr][c0]);
            float4 v1 = *reinterpret_cast<float4*>(&tbuf[rr][c0 + 4]);
            *reinterpret_cast<float4*>(dst) = v0;
            *reinterpret_cast<float4*>(dst + 4) = v1;
            __syncthreads();
        }
    }
}

// aq[n][j] = X[n] . wpack[j]
template<int C, int S, int COLOFF, int O2>
__global__ __launch_bounds__(256, 2) void pq_kernel() {
    __shared__ float As[2][8][132];
    __shared__ float Bs[2][8][132];
    int bb = blockIdx.z;
    int nBase = blockIdx.x * 128;
    int jBase = blockIdx.y * 128;
    const float* Xb = (S == 3 ? g_xin3 : g_xcat) + (size_t)bb * NPTS * S + COLOFF;
    int tid = threadIdx.x;
    int tx = tid & 15, ty = tid >> 4;
    float acc[8][8] = {};

    gemm_mainloop<C, S, C>(Xb + (size_t)nBase * S, g_wpack + (size_t)jBase * C,
                           As, Bs, acc, tid, tx, ty);

#pragma unroll
    for (int i = 0; i < 8; i++) {
        size_t rowoff = ((size_t)bb * NPTS + nBase + ty * 8 + i) * O2 + jBase + tx * 8;
#pragma unroll
        for (int j = 0; j < 8; j++) g_aq[rowoff + j] = acc[i][j];
    }
}

// ---------------- head: bf16 double-split tensor-core GEMM ----------------

__global__ void split_w5_kernel(const float* __restrict__ w5) {
    int id = blockIdx.x * 256 + threadIdx.x;
    float f = w5[id];
    __nv_bfloat16 h = __float2bfloat16(f);
    g_w5h[id] = h;
    g_w5l[id] = __float2bfloat16(f - __bfloat162float(h));
}

#define MMA16816(d, a, b) \
    asm volatile("mma.sync.aligned.m16n8k16.row.col.f32.bf16.bf16.f32 " \
        "{%0,%1,%2,%3}, {%4,%5,%6,%7}, {%8,%9}, {%0,%1,%2,%3};" \
        : "+f"(d[0]), "+f"(d[1]), "+f"(d[2]), "+f"(d[3]) \
        : "r"(a[0]), "r"(a[1]), "r"(a[2]), "r"(a[3]), "r"(b[0]), "r"(b[1]))

// y[o][n] = w5[o].x[n] via Ah*Bh + Ah*Bl + Al*Bh (fp32 acc), fused stats epilogue.
__global__ __launch_bounds__(256, 1) void head_mma_kernel() {
    __shared__ __nv_bfloat16 sAh[128][40];
    __shared__ __nv_bfloat16 sAl[128][40];
    __shared__ __nv_bfloat16 sBh[128][40];
    __shared__ __nv_bfloat16 sBl[128][40];

    int tid = threadIdx.x;
    int wid = tid >> 5, lane = tid & 31;
    int wo = wid >> 2, wn = wid & 3;
    int g = lane >> 2, c0 = (lane & 3) * 2;
    int oBase = blockIdx.x * 128;
    int nTile = blockIdx.y, bb = blockIdx.z;
    int nBase = nTile * 128;

    size_t xoff = ((size_t)bb * NPTS + nBase) * 512;
    const __nv_bfloat16* Bhg = g_xch + xoff;
    const __nv_bfloat16* Blg = g_xcl + xoff;

    float acc[4][4][4] = {};

    for (int kk = 0; kk < 512; kk += 32) {
#pragma unroll
        for (int rep = 0; rep < 2; rep++) {
            int idx = rep * 256 + tid;
            int row = idx >> 2, seg = idx & 3;
            size_t aoff = (size_t)(oBase + row) * 512 + kk + seg * 8;
            size_t boff = (size_t)row * 512 + kk + seg * 8;
            *reinterpret_cast<uint4*>(&sAh[row][seg * 8]) =
                *reinterpret_cast<const uint4*>(g_w5h + aoff);
            *reinterpret_cast<uint4*>(&sAl[row][seg * 8]) =
                *reinterpret_cast<const uint4*>(g_w5l + aoff);
            *reinterpret_cast<uint4*>(&sBh[row][seg * 8]) =
                *reinterpret_cast<const uint4*>(Bhg + boff);
            *reinterpret_cast<uint4*>(&sBl[row][seg * 8]) =
                *reinterpret_cast<const uint4*>(Blg + boff);
        }
        __syncthreads();

#pragma unroll
        for (int ks = 0; ks < 32; ks += 16) {
            unsigned ah[4][4], al[4][4], bh[4][2], bl[4][2];
#pragma unroll
            for (int mi = 0; mi < 4; mi++) {
                int r0 = wo * 64 + mi * 16 + g;
                ah[mi][0] = *(const unsigned*)&sAh[r0][ks + c0];
                ah[mi][1] = *(const unsigned*)&sAh[r0 + 8][ks + c0];
                ah[mi][2] = *(const unsigned*)&sAh[r0][ks + c0 + 8];
                ah[mi][3] = *(const unsigned*)&sAh[r0 + 8][ks + c0 + 8];
                al[mi][0] = *(const unsigned*)&sAl[r0][ks + c0];
                al[mi][1] = *(const unsigned*)&sAl[r0 + 8][ks + c0];
                al[mi][2] = *(const unsigned*)&sAl[r0][ks + c0 + 8];
                al[mi][3] = *(const unsigned*)&sAl[r0 + 8][ks + c0 + 8];
            }
#pragma unroll
            for (int ni = 0; ni < 4; ni++) {
                int nr = wn * 32 + ni * 8 + g;
                bh[ni][0] = *(const unsigned*)&sBh[nr][ks + c0];
                bh[ni][1] = *(const unsigned*)&sBh[nr][ks + c0 + 8];
                bl[ni][0] = *(const unsigned*)&sBl[nr][ks + c0];
                bl[ni][1] = *(const unsigned*)&sBl[nr][ks + c0 + 8];
            }
#pragma unroll
            for (int mi = 0; mi < 4; mi++)
#pragma unroll
                for (int ni = 0; ni < 4; ni++)
                    MMA16816(acc[mi][ni], ah[mi], bh[ni]);
#pragma unroll
            for (int mi = 0; mi < 4; mi++)
#pragma unroll
                for (int ni = 0; ni < 4; ni++)
                    MMA16816(acc[mi][ni], ah[mi], bl[ni]);
#pragma unroll
            for (int mi = 0; mi < 4; mi++)
#pragma unroll
                for (int ni = 0; ni < 4; ni++)
                    MMA16816(acc[mi][ni], al[mi], bh[ni]);
        }
        __syncthreads();
    }

    float* sEp = reinterpret_cast<float*>(&sAh[0][0]);

#pragma unroll
    for (int mi = 0; mi < 4; mi++) {
#pragma unroll
        for (int h = 0; h < 2; h++) {
            float mx = -FLT_MAX, mn = FLT_MAX, s1 = 0.f, s2 = 0.f;
#pragma unroll
            for (int ni = 0; ni < 4; ni++) {
                float v0 = acc[mi][ni][h * 2], v1 = acc[mi][ni][h * 2 + 1];
                mx = fmaxf(mx, fmaxf(v0, v1));
                mn = fminf(mn, fminf(v0, v1));
                s1 += v0 + v1;
                s2 = fmaf(v0, v0, s2);
                s2 = fmaf(v1, v1, s2);
            }
            mx = fmaxf(mx, __shfl_xor_sync(0xffffffffu, mx, 1));
            mn = fminf(mn, __shfl_xor_sync(0xffffffffu, mn, 1));
            s1 += __shfl_xor_sync(0xffffffffu, s1, 1);
            s2 += __shfl_xor_sync(0xffffffffu, s2, 1);
            mx = fmaxf(mx, __shfl_xor_sync(0xffffffffu, mx, 2));
            mn = fminf(mn, __shfl_xor_sync(0xffffffffu, mn, 2));
            s1 += __shfl_xor_sync(0xffffffffu, s1, 2);
            s2 += __shfl_xor_sync(0xffffffffu, s2, 2);
            if ((lane & 3) == 0) {
                int ol = wo * 64 + mi * 16 + h * 8 + g;
                sEp[(wn * 128 + ol) * 4 + 0] = mx;
                sEp[(wn * 128 + ol) * 4 + 1] = mn;
                sEp[(wn * 128 + ol) * 4 + 2] = s1;
                sEp[(wn * 128 + ol) * 4 + 3] = s2;
            }
        }
    }
    __syncthreads();
    if (tid < 128) {
        float mx = sEp[(0 * 128 + tid) * 4 + 0], mn = sEp[(0 * 128 + tid) * 4 + 1];
        float s1 = sEp[(0 * 128 + tid) * 4 + 2], s2 = sEp[(0 * 128 + tid) * 4 + 3];
#pragma unroll
        for (int w = 1; w < 4; w++) {
            mx = fmaxf(mx, sEp[(w * 128 + tid) * 4 + 0]);
            mn = fminf(mn, sEp[(w * 128 + tid) * 4 + 1]);
            s1 += sEp[(w * 128 + tid) * 4 + 2];
            s2 += sEp[(w * 128 + tid) * 4 + 3];
        }
        int o = oBase + tid;
        atomicMaxFloat(&g_fmx[bb * 1024 + o], mx);
        atomicMinFloat(&g_fmn[bb * 1024 + o], mn);
        int slot = bb * 16 + nTile;
        g_pfs1[o * 128 + slot] = s1;
        g_pfs2[o * 128 + slot] = s2;
    }
}

// deterministic head-stat reduction: fixed serial order per channel
__global__ void reduce_final_kernel() {
    int o = blockIdx.x * 256 + threadIdx.x;
    if (o >= 1024) return;
    float s1 = 0.f, s2 = 0.f;
    const float* p1 = g_pfs1 + (size_t)o * 128;
    const float* p2 = g_pfs2 + (size_t)o * 128;
    for (int t = 0; t < 128; t++) { s1 += p1[t]; s2 += p2[t]; }
    g_fs1[o] = s1;
    g_fs2[o] = s2;
}

// ---------------- top-k: MSB radix select, deterministic (value desc, index asc) emission ----------------
__global__ __launch_bounds__(256) void topk_kernel() {
    __shared__ int hist[256];
    __shared__ unsigned int sprefix;
    __shared__ int sneed;
    __shared__ int soutcnt, seqcnt;
    __shared__ int eqidx[64];
    __shared__ unsigned int swk[KNN];
    __shared__ int swi[KNN];

    int row = blockIdx.x;
    const float4* pdrow4 = reinterpret_cast<const float4*>(g_pd + (size_t)row * NPTS);
    int tid = threadIdx.x;
    int lane = tid & 31;

    float fv[8];
    {
        float4 va = pdrow4[tid];
        float4 vb = pdrow4[tid + 256];
        fv[0] = va.x; fv[1] = va.y; fv[2] = va.z; fv[3] = va.w;
        fv[4] = vb.x; fv[5] = vb.y; fv[6] = vb.z; fv[7] = vb.w;
    }
    unsigned int u[8];
#pragma unroll
    for (int j = 0; j < 8; j++) {
        unsigned int fu = __float_as_uint(fv[j]);
        unsigned int m = (fu & 0x80000000u) ? 0xFFFFFFFFu : 0x80000000u;
        u[j] = fu ^ m;
    }

    if (tid == 0) { sprefix = 0; sneed = KNN; }

#pragma unroll
    for (int L = 0; L < 4; L++) {
        int shift = 24 - 8 * L;
        hist[tid] = 0;
        __syncthreads();
        unsigned int pref = sprefix;
#pragma unroll
        for (int j = 0; j < 8; j++) {
            bool part = (L == 0) || ((u[j] >> (shift + 8)) == pref);
            if (part) atomicAdd(&hist[(u[j] >> shift) & 255], 1);
        }
        __syncthreads();
        if (tid < 32) {
            int base = 255 - lane * 8;
            int c[8];
            int lsum = 0;
#pragma unroll
            for (int t = 0; t < 8; t++) { c[t] = hist[base - t]; lsum += c[t]; }
            int inc = lsum;
#pragma unroll
            for (int off = 1; off < 32; off <<= 1) {
                int v = __shfl_up_sync(0xffffffffu, inc, off);
                if (lane >= off) inc += v;
            }
            int excl = inc - lsum;
            int need = sneed;
            if (excl < need && excl + lsum >= need) {
                int run = excl;
                unsigned int bsel = 0;
                int nw = 0;
#pragma unroll
                for (int t = 0; t < 8; t++) {
                    int nb = run + c[t];
                    if (run < need && need <= nb) { bsel = (unsigned)(base - t); nw = need - run; }
                    run = nb;
                }
                sprefix = (pref << 8) | bsel;
                sneed = nw;
            }
        }
        __syncthreads();
    }

    unsigned int T = sprefix;
    int r = sneed;
    if (tid == 0) { soutcnt = 0; seqcnt = 0; }
    __syncthreads();

#pragma unroll
    for (int j = 0; j < 8; j++) {
        int gidx = (j < 4) ? (tid * 4 + j) : (1024 + tid * 4 + (j - 4));
        if (u[j] > T) {
            int p = atomicAdd(&soutcnt, 1);
            swk[p] = u[j];
            swi[p] = gidx;
        } else if (u[j] == T) {
            int p = atomicAdd(&seqcnt, 1);
            if (p < 64) eqidx[p] = gidx;
        }
    }
    __syncthreads();
    if (tid == 0) {
        int base = soutcnt;
        int cnt = seqcnt; if (cnt > 64) cnt = 64;
        for (int s = 0; s < r; s++) {
            int mi = 0;
            for (int t = 1; t < cnt; t++) if (eqidx[t] < eqidx[mi]) mi = t;
            swk[base + s] = T;
            swi[base + s] = eqidx[mi];
            eqidx[mi] = 0x7fffffff;
        }
    }
    __syncthreads();

    if (tid < KNN) {
        unsigned int myk = swk[tid];
        int myi = swi[tid];
        int rank = 0;
#pragma unroll
        for (int t = 0; t < KNN; t++) {
            unsigned int ok = swk[t];
            int oi = swi[t];
            rank += (ok > myk || (ok == myk && oi < myi)) ? 1 : 0;
        }
        g_idx[row * KNN + rank] = myi;
    }
}

// ---------------- remaining pipeline kernels ----------------

__global__ void wpack_kernel(const float* __restrict__ w, int C, int O) {
    int id = blockIdx.x * blockDim.x + threadIdx.x;
    int tot = 2 * O * C;
    if (id >= tot) return;
    int j = id / C, c = id - j * C;
    g_wpack[id] = (j < O) ? w[j * 2 * C + c] : w[(j - O) * 2 * C + C + c];
}

__global__ __launch_bounds__(256) void gather_kernel(int O) {
    int G = 256 / O;
    int NB = 4 * G;
    __shared__ int sidx[16 * KNN];
    int nBase = blockIdx.x * NB;
    int tid = threadIdx.x;
    int cnt = NB * KNN;
    for (int i = tid; i < cnt; i += 256) sidx[i] = g_idx[nBase * KNN + i];
    __syncthreads();

    int o = tid & (O - 1);
    int sub = tid / O;
    int O2 = 2 * O;
    int bbase = (nBase >> 11) << 11;
    float ts1 = 0.f, ts2 = 0.f;

#pragma unroll
    for (int ii = 0; ii < 4; ii++) {
        int local = sub * 4 + ii;
        int r = nBase + local;
        float a = g_aq[(size_t)r * O2 + o];
        float q = g_aq[(size_t)r * O2 + O + o];
        float p = a - q;
        float mx = -FLT_MAX, mn = FLT_MAX;
#pragma unroll
        for (int k = 0; k < KNN; k++) {
            int m = sidx[local * KNN + k];
            float qv = g_aq[(size_t)(bbase + m) * O2 + O + o];
            float z = p + qv;
            mx = fmaxf(mx, z);
            mn = fminf(mn, z);
            ts1 += z;
            ts2 = fmaf(z, z, ts2);
        }
        g_mx[(size_t)r * O + o] = mx;
        g_mn[(size_t)r * O + o] = mn;
    }
    int slot = blockIdx.x * G + sub;
    g_ps1[(size_t)o * 4096 + slot] = ts1;
    g_ps2[(size_t)o * 4096 + slot] = ts2;
}

__global__ __launch_bounds__(256) void reduce_stats_kernel() {
    __shared__ float sh1[256], sh2[256];
    int o = blockIdx.x;
    int tid = threadIdx.x;
    const float* p1 = g_ps1 + (size_t)o * 4096;
    const float* p2 = g_ps2 + (size_t)o * 4096;
    float s1 = 0.f, s2 = 0.f;
    for (int t = 0; t < 16; t++) { s1 += p1[tid + 256 * t]; s2 += p2[tid + 256 * t]; }
    sh1[tid] = s1; sh2[tid] = s2;
    __syncthreads();
    for (int s = 128; s; s >>= 1) {
        if (tid < s) { sh1[tid] += sh1[tid + s]; sh2[tid] += sh2[tid + s]; }
        __syncthreads();
    }
    if (tid == 0) { g_s1[o] = sh1[0]; g_s2[o] = sh2[0]; }
}

// BN + LeakyReLU on pooled value; write fp32 result AND its bf16 hi/lo split (head operands)
__global__ void finalize_kernel(int O, int colbase,
                                const float* __restrict__ gamma,
                                const float* __restrict__ beta) {
    int id = blockIdx.x * 256 + threadIdx.x;
    int r = id / O, o = id - r * O;
    const float invCNT = 1.f / (float)(BATCH * NPTS * KNN);
    float mean = g_s1[o] * invCNT;
    float var = g_s2[o] * invCNT - mean * mean;
    float scale = gamma[o] * rsqrtf(var + EPSBN);
    float shift = beta[o] - mean * scale;
    float sel = (scale >= 0.f) ? g_mx[(size_t)r * O + o] : g_mn[(size_t)r * O + o];
    float v = fmaf(scale, sel, shift);
    float res = (v >= 0.f) ? v : 0.2f * v;
    size_t oidx = (size_t)r * 512 + colbase + o;
    g_xcat[oidx] = res;
    __nv_bfloat16 h = __float2bfloat16(res);
    g_xch[oidx] = h;
    g_xcl[oidx] = __float2bfloat16(res - __bfloat162float(h));
}

__global__ void init_final_kernel() {
    int id = blockIdx.x * blockDim.x + threadIdx.x;
    if (id < BATCH * 1024) { g_fmx[id] = -FLT_MAX; g_fmn[id] = FLT_MAX; }
}

__global__ void out_kernel(const float* __restrict__ g5, const float* __restrict__ b5,
                           float* __restrict__ out) {
    int id = blockIdx.x * blockDim.x + threadIdx.x;
    if (id >= BATCH * 1024) return;
    int o = id & 1023;
    const float invCNT = 1.f / (float)(BATCH * NPTS);
    float mean = g_fs1[o] * invCNT;
    float var = g_fs2[o] * invCNT - mean * mean;
    float scale = g5[o] * rsqrtf(var + EPSBN);
    float shift = b5[o] - mean * scale;
    float sel = (scale >= 0.f) ? g_fmx[id] : g_fmn[id];
    float v = fmaf(scale, sel, shift);
    out[id] = (v >= 0.f) ? v : 0.2f * v;
}

// ---------------- host driver ----------------

extern "C" void kernel_launch(void* const* d_in, const int* in_sizes, int n_in,
                              void* d_out, int out_size) {
    const float* x  = (const float*)d_in[0];
    const float* w1 = (const float*)d_in[1];
    const float* g1 = (const float*)d_in[2];
    const float* b1 = (const float*)d_in[3];
    const float* w2 = (const float*)d_in[4];
    const float* g2 = (const float*)d_in[5];
    const float* b2 = (const float*)d_in[6];
    const float* w3 = (const float*)d_in[7];
    const float* g3 = (const float*)d_in[8];
    const float* b3 = (const float*)d_in[9];
    const float* w4 = (const float*)d_in[10];
    const float* g4 = (const float*)d_in[11];
    const float* b4 = (const float*)d_in[12];
    const float* w5 = (const float*)d_in[13];
    const float* g5 = (const float*)d_in[14];
    const float* b5 = (const float*)d_in[15];

    transpose_in_kernel<<<(BATCH * 3 * NPTS + 255) / 256, 256>>>(x);
    split_w5_kernel<<<(1024 * 512) / 256, 256>>>(w5);

    dim3 gramGrid(136, 1, BATCH);

    // ---- layer 1: C=3, S=3, O=64 ----
    sq_kernel<<<(BATCH * NPTS) / 8, 256>>>(0, 0, 3, 3);
    gram1_kernel<<<dim3(NPTS / 32, BATCH), 256>>>();
    topk_kernel<<<BATCH * NPTS, 256>>>();
    wpack_kernel<<<(128 * 3 + 255) / 256, 256>>>(w1, 3, 64);
    pq_kernel<3, 3, 0, 128><<<dim3(NPTS / 128, 1, BATCH), 256>>>();
    gather_kernel<<<(BATCH * NPTS * 64) / 1024, 256>>>(64);
    reduce_stats_kernel<<<64, 256>>>();
    finalize_kernel<<<(BATCH * NPTS * 64) / 256, 256>>>(64, 0, g1, b1);

    // ---- layer 2: C=64, coloff=0, O=64 ----
    sq_kernel<<<(BATCH * NPTS) / 8, 256>>>(1, 0, 64, 512);
    gram_kernel<64, 512, 0><<<gramGrid, 256>>>();
    topk_kernel<<<BATCH * NPTS, 256>>>();
    wpack_kernel<<<(128 * 64 + 255) / 256, 256>>>(w2, 64, 64);
    pq_kernel<64, 512, 0, 128><<<dim3(NPTS / 128, 1, BATCH), 256>>>();
    gather_kernel<<<(BATCH * NPTS * 64) / 1024, 256>>>(64);
    reduce_stats_kernel<<<64, 256>>>();
    finalize_kernel<<<(BATCH * NPTS * 64) / 256, 256>>>(64, 64, g2, b2);

    // ---- layer 3: C=64, coloff=64, O=128 ----
    sq_kernel<<<(BATCH * NPTS) / 8, 256>>>(1, 64, 64, 512);
    gram_kernel<64, 512, 64><<<gramGrid, 256>>>();
    topk_kernel<<<BATCH * NPTS, 256>>>();
    wpack_kernel<<<(256 * 64 + 255) / 256, 256>>>(w3, 64, 128);
    pq_kernel<64, 512, 64, 256><<<dim3(NPTS / 128, 2, BATCH), 256>>>();
    gather_kernel<<<(BATCH * NPTS * 128) / 1024, 256>>>(128);
    reduce_stats_kernel<<<128, 256>>>();
    finalize_kernel<<<(BATCH * NPTS * 128) / 256, 256>>>(128, 128, g3, b3);

    // ---- layer 4: C=128, coloff=128, O=256 ----
    sq_kernel<<<(BATCH * NPTS) / 8, 256>>>(1, 128, 128, 512);
    gram_kernel<128, 512, 128><<<gramGrid, 256>>>();
    topk_kernel<<<BATCH * NPTS, 256>>>();
    wpack_kernel<<<(512 * 128 + 255) / 256, 256>>>(w4, 128, 256);
    pq_kernel<128, 512, 128, 512><<<dim3(NPTS / 128, 4, BATCH), 256>>>();
    gather_kernel<<<(BATCH * NPTS * 256) / 1024, 256>>>(256);
    reduce_stats_kernel<<<256, 256>>>();
    finalize_kernel<<<(BATCH * NPTS * 256) / 256, 256>>>(256, 256, g4, b4);

    // ---- head: bf16 double-split tensor-core GEMM ----
    init_final_kernel<<<32, 256>>>();
    head_mma_kernel<<<dim3(1024 / 128, NPTS / 128, BATCH), 256>>>();
    reduce_final_kernel<<<4, 256>>>();
    out_kernel<<<32, 256>>>(g5, b5, (float*)d_out);
}

// round 14
// speedup vs baseline: 1.5856x; 1.5856x over previous
#include <cuda_runtime.h>
#include <cuda_bf16.h>
#include <float.h>

#define BATCH 8
#define NPTS  2048
#define KNN   20
#define EPSBN 1e-5f

// R13 = R12 resubmitted unchanged: controlled re-bench to separate DVFS/run noise
// from a real regression (only gram1 changed in R12 and ncu shows it got 3.3x faster
// with bit-identical output; the +670us total is not attributable to any code path).

// ---------------- scratch (device globals; no runtime allocation) ----------------
__device__ float g_xin3[BATCH * NPTS * 3];
__device__ float g_xcat[BATCH * NPTS * 512];
__device__ float g_sq[BATCH * NPTS];
__device__ float g_pd[(size_t)BATCH * NPTS * NPTS];
__device__ int   g_idx[BATCH * NPTS * KNN];
__device__ float g_wpack[512 * 256];
__device__ float g_aq[(size_t)BATCH * NPTS * 512];
__device__ float g_mx[(size_t)BATCH * NPTS * 256];
__device__ float g_mn[(size_t)BATCH * NPTS * 256];
__device__ float g_s1[256];
__device__ float g_s2[256];
__device__ float g_fmx[BATCH * 1024];
__device__ float g_fmn[BATCH * 1024];
__device__ float g_fs1[1024];
__device__ float g_fs2[1024];
// deterministic-reduction scratch (one slot per contributor; NO float atomics anywhere)
__device__ float g_ps1[256 * 4096];
__device__ float g_ps2[256 * 4096];
__device__ float g_pfs1[1024 * 128];
__device__ float g_pfs2[1024 * 128];
// head bf16 double-split operands
__device__ __nv_bfloat16 g_w5h[1024 * 512];
__device__ __nv_bfloat16 g_w5l[1024 * 512];
__device__ __nv_bfloat16 g_xch[(size_t)BATCH * NPTS * 512];
__device__ __nv_bfloat16 g_xcl[(size_t)BATCH * NPTS * 512];

// ---------------- helpers (max/min atomics are order-independent => deterministic) ----------------
__device__ __forceinline__ void atomicMaxFloat(float* a, float v) {
    if (v >= 0.f) atomicMax((int*)a, __float_as_int(v));
    else          atomicMin((unsigned int*)a, __float_as_uint(v));
}
__device__ __forceinline__ void atomicMinFloat(float* a, float v) {
    if (v >= 0.f) atomicMin((int*)a, __float_as_int(v));
    else          atomicMax((unsigned int*)a, __float_as_uint(v));
}

// ---------------- small kernels ----------------

__global__ void transpose_in_kernel(const float* __restrict__ x) {
    int id = blockIdx.x * blockDim.x + threadIdx.x;
    if (id >= BATCH * 3 * NPTS) return;
    int n = id % NPTS;
    int c = (id / NPTS) % 3;
    int b = id / (3 * NPTS);
    g_xin3[((size_t)(b * NPTS + n)) * 3 + c] = x[id];
}

__global__ void sq_kernel(int src, int coloff, int C, int S) {
    int row = blockIdx.x * 8 + (threadIdx.x >> 5);
    int lane = threadIdx.x & 31;
    const float* X = (src ? g_xcat : g_xin3) + (size_t)row * S + coloff;
    float s = 0.f;
    for (int c = lane; c < C; c += 32) s = fmaf(X[c], X[c], s);
#pragma unroll
    for (int off = 16; off; off >>= 1) s += __shfl_down_sync(0xffffffffu, s, off);
    if (lane == 0) g_sq[row] = s;
}

// ---------------- layer-1 gram v2: 32 n-rows per block, smem-staged m-chunks ----------------
// Value expression identical to the zero-padded tile (fmaf chain, 2*acc - sn - sm)
// => pd bit-identical. Block reads x/sq once per 256-m chunk; writes coalesced.
__global__ __launch_bounds__(256) void gram1_kernel() {
    __shared__ float sx[256 * 3];
    __shared__ float ssq[256];
    int bb = blockIdx.y;
    int n0 = blockIdx.x * 32;
    int tid = threadIdx.x, lane = tid & 31, w = tid >> 5;
    const float* Xb  = g_xin3 + (size_t)bb * NPTS * 3;
    const float* sqb = g_sq + bb * NPTS;

    float xn[4][3], sn[4];
#pragma unroll
    for (int r = 0; r < 4; r++) {
        int n = n0 + w * 4 + r;
        xn[r][0] = Xb[n * 3 + 0];
        xn[r][1] = Xb[n * 3 + 1];
        xn[r][2] = Xb[n * 3 + 2];
        sn[r] = sqb[n];
    }

    for (int mc = 0; mc < NPTS; mc += 256) {
        sx[tid]       = Xb[mc * 3 + tid];
        sx[256 + tid] = Xb[mc * 3 + 256 + tid];
        sx[512 + tid] = Xb[mc * 3 + 512 + tid];
        ssq[tid]      = sqb[mc + tid];
        __syncthreads();
#pragma unroll
        for (int r = 0; r < 4; r++) {
            int n = n0 + w * 4 + r;
            float* row = g_pd + ((size_t)bb * NPTS + n) * NPTS + mc;
            float x0 = xn[r][0], x1 = xn[r][1], x2 = xn[r][2], s = sn[r];
#pragma unroll
            for (int mm0 = 0; mm0 < 256; mm0 += 32) {
                int mm = mm0 + lane;
                float acc = 0.f;
                acc = fmaf(x0, sx[mm * 3 + 0], acc);
                acc = fmaf(x1, sx[mm * 3 + 1], acc);
                acc = fmaf(x2, sx[mm * 3 + 2], acc);
                row[mm] = 2.f * acc - s - ssq[mm];
            }
        }
        __syncthreads();
    }
}

// ---------------- 128x128x8 SGEMM mainloop, double-buffered (layers 2-4) ----------------

template<int KDIM, int ASTR, int BSTR>
__device__ __forceinline__ void gemm_mainloop(const float* __restrict__ A,
                                              const float* __restrict__ B,
                                              float (&As)[2][8][132], float (&Bs)[2][8][132],
                                              float (&acc)[8][8],
                                              int tid, int tx, int ty) {
    constexpr bool VEC = (KDIM % 8 == 0) && (ASTR % 4 == 0) && (BSTR % 4 == 0);
    constexpr int NT = (KDIM + 7) / 8;
    int ar = tid >> 1;
    int ac = (tid & 1) * 4;
    float ra[4], rb[4];

    if (VEC) {
        float4 a4 = *reinterpret_cast<const float4*>(A + (size_t)ar * ASTR + ac);
        float4 b4 = *reinterpret_cast<const float4*>(B + (size_t)ar * BSTR + ac);
        ra[0] = a4.x; ra[1] = a4.y; ra[2] = a4.z; ra[3] = a4.w;
        rb[0] = b4.x; rb[1] = b4.y; rb[2] = b4.z; rb[3] = b4.w;
    } else {
#pragma unroll
        for (int j = 0; j < 4; j++) {
            int gc = ac + j;
            ra[j] = (gc < KDIM) ? A[(size_t)ar * ASTR + gc] : 0.f;
            rb[j] = (gc < KDIM) ? B[(size_t)ar * BSTR + gc] : 0.f;
        }
    }
#pragma unroll
    for (int j = 0; j < 4; j++) { As[0][ac + j][ar] = ra[j]; Bs[0][ac + j][ar] = rb[j]; }
    __syncthreads();

    for (int t = 0; t < NT; t++) {
        if (t + 1 < NT) {
            int kk = (t + 1) * 8;
            if (VEC) {
                float4 a4 = *reinterpret_cast<const float4*>(A + (size_t)ar * ASTR + kk + ac);
                float4 b4 = *reinterpret_cast<const float4*>(B + (size_t)ar * BSTR + kk + ac);
                ra[0] = a4.x; ra[1] = a4.y; ra[2] = a4.z; ra[3] = a4.w;
                rb[0] = b4.x; rb[1] = b4.y; rb[2] = b4.z; rb[3] = b4.w;
            } else {
#pragma unroll
                for (int j = 0; j < 4; j++) {
                    int gc = kk + ac + j;
                    ra[j] = (gc < KDIM) ? A[(size_t)ar * ASTR + gc] : 0.f;
                    rb[j] = (gc < KDIM) ? B[(size_t)ar * BSTR + gc] : 0.f;
                }
            }
        }
        int cur = t & 1;
#pragma unroll
        for (int k = 0; k < 8; k++) {
            float a[8], b[8];
#pragma unroll
            for (int i = 0; i < 8; i++) a[i] = As[cur][k][ty * 8 + i];
#pragma unroll
            for (int i = 0; i < 8; i++) b[i] = Bs[cur][k][tx * 8 + i];
#pragma unroll
            for (int i = 0; i < 8; i++)
#pragma unroll
                for (int j = 0; j < 8; j++)
                    acc[i][j] = fmaf(a[i], b[j], acc[i][j]);
        }
        if (t + 1 < NT) {
            int nxt = (t + 1) & 1;
#pragma unroll
            for (int j = 0; j < 4; j++) { As[nxt][ac + j][ar] = ra[j]; Bs[nxt][ac + j][ar] = rb[j]; }
            __syncthreads();
        }
    }
}

// pd = 2*X Xt - sq_n - sq_m; triangle blocks; mirror written COALESCED via smem transpose.
template<int C, int S, int COLOFF>
__global__ __launch_bounds__(256, 2) void gram_kernel() {
    __shared__ float As[2][8][132];
    __shared__ float Bs[2][8][132];
    __shared__ float tbuf[16][136];
    int bb = blockIdx.z;
    int t = blockIdx.x, br = 0;
    while (t >= 16 - br) { t -= 16 - br; br++; }
    int bc = br + t;
    int nBase = br * 128, mBase = bc * 128;

    const float* Xb = g_xcat + (size_t)bb * NPTS * S + COLOFF;
    int tid = threadIdx.x;
    int tx = tid & 15, ty = tid >> 4;
    float acc[8][8] = {};

    gemm_mainloop<C, S, S>(Xb + (size_t)nBase * S, Xb + (size_t)mBase * S,
                           As, Bs, acc, tid, tx, ty);

    const float* sqb = g_sq + bb * NPTS;
    float* pdb = g_pd + (size_t)bb * NPTS * NPTS;

    float sn_r[8], sqm_r[8];
#pragma unroll
    for (int i = 0; i < 8; i++) sn_r[i] = sqb[nBase + ty * 8 + i];
#pragma unroll
    for (int j = 0; j < 8; j++) sqm_r[j] = sqb[mBase + tx * 8 + j];

#pragma unroll
    for (int i = 0; i < 8; i++) {
        int n = nBase + ty * 8 + i;
#pragma unroll
        for (int j = 0; j < 8; j++) {
            pdb[(size_t)n * NPTS + mBase + tx * 8 + j] = 2.f * acc[i][j] - sn_r[i] - sqm_r[j];
        }
    }

    if (br != bc) {
        for (int s = 0; s < 8; s++) {
            if ((tx >> 1) == s) {
#pragma unroll
                for (int i = 0; i < 8; i++)
#pragma unroll
                    for (int j = 0; j < 8; j++)
                        tbuf[(tx & 1) * 8 + j][ty * 8 + i] = 2.f * acc[i][j] - sn_r[i] - sqm_r[j];
            }
            __syncthreads();
            int rr = tid >> 4;
            int c0 = (tid & 15) * 8;
            float* dst = pdb + (size_t)(mBase + s * 16 + rr) * NPTS + nBase + c0;
            float4 v0 = *reinterpret_cast<float4*>(&tbuf[rr][c0]);
            float4 v1 = *reinterpret_cast<float4*>(&tbuf[rr][c0 + 4]);
            *reinterpret_cast<float4*>(dst) = v0;
            *reinterpret_cast<float4*>(dst + 4) = v1;
            __syncthreads();
        }
    }
}

// aq[n][j] = X[n] . wpack[j]
template<int C, int S, int COLOFF, int O2>
__global__ __launch_bounds__(256, 2) void pq_kernel() {
    __shared__ float As[2][8][132];
    __shared__ float Bs[2][8][132];
    int bb = blockIdx.z;
    int nBase = blockIdx.x * 128;
    int jBase = blockIdx.y * 128;
    const float* Xb = (S == 3 ? g_xin3 : g_xcat) + (size_t)bb * NPTS * S + COLOFF;
    int tid = threadIdx.x;
    int tx = tid & 15, ty = tid >> 4;
    float acc[8][8] = {};

    gemm_mainloop<C, S, C>(Xb + (size_t)nBase * S, g_wpack + (size_t)jBase * C,
                           As, Bs, acc, tid, tx, ty);

#pragma unroll
    for (int i = 0; i < 8; i++) {
        size_t rowoff = ((size_t)bb * NPTS + nBase + ty * 8 + i) * O2 + jBase + tx * 8;
#pragma unroll
        for (int j = 0; j < 8; j++) g_aq[rowoff + j] = acc[i][j];
    }
}

// ---------------- head: bf16 double-split tensor-core GEMM ----------------

__global__ void split_w5_kernel(const float* __restrict__ w5) {
    int id = blockIdx.x * 256 + threadIdx.x;
    float f = w5[id];
    __nv_bfloat16 h = __float2bfloat16(f);
    g_w5h[id] = h;
    g_w5l[id] = __float2bfloat16(f - __bfloat162float(h));
}

#define MMA16816(d, a, b) \
    asm volatile("mma.sync.aligned.m16n8k16.row.col.f32.bf16.bf16.f32 " \
        "{%0,%1,%2,%3}, {%4,%5,%6,%7}, {%8,%9}, {%0,%1,%2,%3};" \
        : "+f"(d[0]), "+f"(d[1]), "+f"(d[2]), "+f"(d[3]) \
        : "r"(a[0]), "r"(a[1]), "r"(a[2]), "r"(a[3]), "r"(b[0]), "r"(b[1]))

// y[o][n] = w5[o].x[n] via Ah*Bh + Ah*Bl + Al*Bh (fp32 acc), fused stats epilogue.
__global__ __launch_bounds__(256, 1) void head_mma_kernel() {
    __shared__ __nv_bfloat16 sAh[128][40];
    __shared__ __nv_bfloat16 sAl[128][40];
    __shared__ __nv_bfloat16 sBh[128][40];
    __shared__ __nv_bfloat16 sBl[128][40];

    int tid = threadIdx.x;
    int wid = tid >> 5, lane = tid & 31;
    int wo = wid >> 2, wn = wid & 3;
    int g = lane >> 2, c0 = (lane & 3) * 2;
    int oBase = blockIdx.x * 128;
    int nTile = blockIdx.y, bb = blockIdx.z;
    int nBase = nTile * 128;

    size_t xoff = ((size_t)bb * NPTS + nBase) * 512;
    const __nv_bfloat16* Bhg = g_xch + xoff;
    const __nv_bfloat16* Blg = g_xcl + xoff;

    float acc[4][4][4] = {};

    for (int kk = 0; kk < 512; kk += 32) {
#pragma unroll
        for (int rep = 0; rep < 2; rep++) {
            int idx = rep * 256 + tid;
            int row = idx >> 2, seg = idx & 3;
            size_t aoff = (size_t)(oBase + row) * 512 + kk + seg * 8;
            size_t boff = (size_t)row * 512 + kk + seg * 8;
            *reinterpret_cast<uint4*>(&sAh[row][seg * 8]) =
                *reinterpret_cast<const uint4*>(g_w5h + aoff);
            *reinterpret_cast<uint4*>(&sAl[row][seg * 8]) =
                *reinterpret_cast<const uint4*>(g_w5l + aoff);
            *reinterpret_cast<uint4*>(&sBh[row][seg * 8]) =
                *reinterpret_cast<const uint4*>(Bhg + boff);
            *reinterpret_cast<uint4*>(&sBl[row][seg * 8]) =
                *reinterpret_cast<const uint4*>(Blg + boff);
        }
        __syncthreads();

#pragma unroll
        for (int ks = 0; ks < 32; ks += 16) {
            unsigned ah[4][4], al[4][4], bh[4][2], bl[4][2];
#pragma unroll
            for (int mi = 0; mi < 4; mi++) {
                int r0 = wo * 64 + mi * 16 + g;
                ah[mi][0] = *(const unsigned*)&sAh[r0][ks + c0];
                ah[mi][1] = *(const unsigned*)&sAh[r0 + 8][ks + c0];
                ah[mi][2] = *(const unsigned*)&sAh[r0][ks + c0 + 8];
                ah[mi][3] = *(const unsigned*)&sAh[r0 + 8][ks + c0 + 8];
                al[mi][0] = *(const unsigned*)&sAl[r0][ks + c0];
                al[mi][1] = *(const unsigned*)&sAl[r0 + 8][ks + c0];
                al[mi][2] = *(const unsigned*)&sAl[r0][ks + c0 + 8];
                al[mi][3] = *(const unsigned*)&sAl[r0 + 8][ks + c0 + 8];
            }
#pragma unroll
            for (int ni = 0; ni < 4; ni++) {
                int nr = wn * 32 + ni * 8 + g;
                bh[ni][0] = *(const unsigned*)&sBh[nr][ks + c0];
                bh[ni][1] = *(const unsigned*)&sBh[nr][ks + c0 + 8];
                bl[ni][0] = *(const unsigned*)&sBl[nr][ks + c0];
                bl[ni][1] = *(const unsigned*)&sBl[nr][ks + c0 + 8];
            }
#pragma unroll
            for (int mi = 0; mi < 4; mi++)
#pragma unroll
                for (int ni = 0; ni < 4; ni++)
                    MMA16816(acc[mi][ni], ah[mi], bh[ni]);
#pragma unroll
            for (int mi = 0; mi < 4; mi++)
#pragma unroll
                for (int ni = 0; ni < 4; ni++)
                    MMA16816(acc[mi][ni], ah[mi], bl[ni]);
#pragma unroll
            for (int mi = 0; mi < 4; mi++)
#pragma unroll
                for (int ni = 0; ni < 4; ni++)
                    MMA16816(acc[mi][ni], al[mi], bh[ni]);
        }
        __syncthreads();
    }

    float* sEp = reinterpret_cast<float*>(&sAh[0][0]);

#pragma unroll
    for (int mi = 0; mi < 4; mi++) {
#pragma unroll
        for (int h = 0; h < 2; h++) {
            float mx = -FLT_MAX, mn = FLT_MAX, s1 = 0.f, s2 = 0.f;
#pragma unroll
            for (int ni = 0; ni < 4; ni++) {
                float v0 = acc[mi][ni][h * 2], v1 = acc[mi][ni][h * 2 + 1];
                mx = fmaxf(mx, fmaxf(v0, v1));
                mn = fminf(mn, fminf(v0, v1));
                s1 += v0 + v1;
                s2 = fmaf(v0, v0, s2);
                s2 = fmaf(v1, v1, s2);
            }
            mx = fmaxf(mx, __shfl_xor_sync(0xffffffffu, mx, 1));
            mn = fminf(mn, __shfl_xor_sync(0xffffffffu, mn, 1));
            s1 += __shfl_xor_sync(0xffffffffu, s1, 1);
            s2 += __shfl_xor_sync(0xffffffffu, s2, 1);
            mx = fmaxf(mx, __shfl_xor_sync(0xffffffffu, mx, 2));
            mn = fminf(mn, __shfl_xor_sync(0xffffffffu, mn, 2));
            s1 += __shfl_xor_sync(0xffffffffu, s1, 2);
            s2 += __shfl_xor_sync(0xffffffffu, s2, 2);
            if ((lane & 3) == 0) {
                int ol = wo * 64 + mi * 16 + h * 8 + g;
                sEp[(wn * 128 + ol) * 4 + 0] = mx;
                sEp[(wn * 128 + ol) * 4 + 1] = mn;
                sEp[(wn * 128 + ol) * 4 + 2] = s1;
                sEp[(wn * 128 + ol) * 4 + 3] = s2;
            }
        }
    }
    __syncthreads();
    if (tid < 128) {
        float mx = sEp[(0 * 128 + tid) * 4 + 0], mn = sEp[(0 * 128 + tid) * 4 + 1];
        float s1 = sEp[(0 * 128 + tid) * 4 + 2], s2 = sEp[(0 * 128 + tid) * 4 + 3];
#pragma unroll
        for (int w = 1; w < 4; w++) {
            mx = fmaxf(mx, sEp[(w * 128 + tid) * 4 + 0]);
            mn = fminf(mn, sEp[(w * 128 + tid) * 4 + 1]);
            s1 += sEp[(w * 128 + tid) * 4 + 2];
            s2 += sEp[(w * 128 + tid) * 4 + 3];
        }
        int o = oBase + tid;
        atomicMaxFloat(&g_fmx[bb * 1024 + o], mx);
        atomicMinFloat(&g_fmn[bb * 1024 + o], mn);
        int slot = bb * 16 + nTile;
        g_pfs1[o * 128 + slot] = s1;
        g_pfs2[o * 128 + slot] = s2;
    }
}

// deterministic head-stat reduction: fixed serial order per channel
__global__ void reduce_final_kernel() {
    int o = blockIdx.x * 256 + threadIdx.x;
    if (o >= 1024) return;
    float s1 = 0.f, s2 = 0.f;
    const float* p1 = g_pfs1 + (size_t)o * 128;
    const float* p2 = g_pfs2 + (size_t)o * 128;
    for (int t = 0; t < 128; t++) { s1 += p1[t]; s2 += p2[t]; }
    g_fs1[o] = s1;
    g_fs2[o] = s2;
}

// ---------------- top-k: MSB radix select, deterministic (value desc, index asc) emission ----------------
__global__ __launch_bounds__(256) void topk_kernel() {
    __shared__ int hist[256];
    __shared__ unsigned int sprefix;
    __shared__ int sneed;
    __shared__ int soutcnt, seqcnt;
    __shared__ int eqidx[64];
    __shared__ unsigned int swk[KNN];
    __shared__ int swi[KNN];

    int row = blockIdx.x;
    const float4* pdrow4 = reinterpret_cast<const float4*>(g_pd + (size_t)row * NPTS);
    int tid = threadIdx.x;
    int lane = tid & 31;

    float fv[8];
    {
        float4 va = pdrow4[tid];
        float4 vb = pdrow4[tid + 256];
        fv[0] = va.x; fv[1] = va.y; fv[2] = va.z; fv[3] = va.w;
        fv[4] = vb.x; fv[5] = vb.y; fv[6] = vb.z; fv[7] = vb.w;
    }
    unsigned int u[8];
#pragma unroll
    for (int j = 0; j < 8; j++) {
        unsigned int fu = __float_as_uint(fv[j]);
        unsigned int m = (fu & 0x80000000u) ? 0xFFFFFFFFu : 0x80000000u;
        u[j] = fu ^ m;
    }

    if (tid == 0) { sprefix = 0; sneed = KNN; }

#pragma unroll
    for (int L = 0; L < 4; L++) {
        int shift = 24 - 8 * L;
        hist[tid] = 0;
        __syncthreads();
        unsigned int pref = sprefix;
#pragma unroll
        for (int j = 0; j < 8; j++) {
            bool part = (L == 0) || ((u[j] >> (shift + 8)) == pref);
            if (part) atomicAdd(&hist[(u[j] >> shift) & 255], 1);
        }
        __syncthreads();
        if (tid < 32) {
            int base = 255 - lane * 8;
            int c[8];
            int lsum = 0;
#pragma unroll
            for (int t = 0; t < 8; t++) { c[t] = hist[base - t]; lsum += c[t]; }
            int inc = lsum;
#pragma unroll
            for (int off = 1; off < 32; off <<= 1) {
                int v = __shfl_up_sync(0xffffffffu, inc, off);
                if (lane >= off) inc += v;
            }
            int excl = inc - lsum;
            int need = sneed;
            if (excl < need && excl + lsum >= need) {
                int run = excl;
                unsigned int bsel = 0;
                int nw = 0;
#pragma unroll
                for (int t = 0; t < 8; t++) {
                    int nb = run + c[t];
                    if (run < need && need <= nb) { bsel = (unsigned)(base - t); nw = need - run; }
                    run = nb;
                }
                sprefix = (pref << 8) | bsel;
                sneed = nw;
            }
        }
        __syncthreads();
    }

    unsigned int T = sprefix;
    int r = sneed;
    if (tid == 0) { soutcnt = 0; seqcnt = 0; }
    __syncthreads();

#pragma unroll
    for (int j = 0; j < 8; j++) {
        int gidx = (j < 4) ? (tid * 4 + j) : (1024 + tid * 4 + (j - 4));
        if (u[j] > T) {
            int p = atomicAdd(&soutcnt, 1);
            swk[p] = u[j];
            swi[p] = gidx;
        } else if (u[j] == T) {
            int p = atomicAdd(&seqcnt, 1);
            if (p < 64) eqidx[p] = gidx;
        }
    }
    __syncthreads();
    if (tid == 0) {
        int base = soutcnt;
        int cnt = seqcnt; if (cnt > 64) cnt = 64;
        for (int s = 0; s < r; s++) {
            int mi = 0;
            for (int t = 1; t < cnt; t++) if (eqidx[t] < eqidx[mi]) mi = t;
            swk[base + s] = T;
            swi[base + s] = eqidx[mi];
            eqidx[mi] = 0x7fffffff;
        }
    }
    __syncthreads();

    if (tid < KNN) {
        unsigned int myk = swk[tid];
        int myi = swi[tid];
        int rank = 0;
#pragma unroll
        for (int t = 0; t < KNN; t++) {
            unsigned int ok = swk[t];
            int oi = swi[t];
            rank += (ok > myk || (ok == myk && oi < myi)) ? 1 : 0;
        }
        g_idx[row * KNN + rank] = myi;
    }
}

// ---------------- remaining pipeline kernels ----------------

__global__ void wpack_kernel(const float* __restrict__ w, int C, int O) {
    int id = blockIdx.x * blockDim.x + threadIdx.x;
    int tot = 2 * O * C;
    if (id >= tot) return;
    int j = id / C, c = id - j * C;
    g_wpack[id] = (j < O) ? w[j * 2 * C + c] : w[(j - O) * 2 * C + C + c];
}

__global__ __launch_bounds__(256) void gather_kernel(int O) {
    int G = 256 / O;
    int NB = 4 * G;
    __shared__ int sidx[16 * KNN];
    int nBase = blockIdx.x * NB;
    int tid = threadIdx.x;
    int cnt = NB * KNN;
    for (int i = tid; i < cnt; i += 256) sidx[i] = g_idx[nBase * KNN + i];
    __syncthreads();

    int o = tid & (O - 1);
    int sub = tid / O;
    int O2 = 2 * O;
    int bbase = (nBase >> 11) << 11;
    float ts1 = 0.f, ts2 = 0.f;

#pragma unroll
    for (int ii = 0; ii < 4; ii++) {
        int local = sub * 4 + ii;
        int r = nBase + local;
        float a = g_aq[(size_t)r * O2 + o];
        float q = g_aq[(size_t)r * O2 + O + o];
        float p = a - q;
        float mx = -FLT_MAX, mn = FLT_MAX;
#pragma unroll
        for (int k = 0; k < KNN; k++) {
            int m = sidx[local * KNN + k];
            float qv = g_aq[(size_t)(bbase + m) * O2 + O + o];
            float z = p + qv;
            mx = fmaxf(mx, z);
            mn = fminf(mn, z);
            ts1 += z;
            ts2 = fmaf(z, z, ts2);
        }
        g_mx[(size_t)r * O + o] = mx;
        g_mn[(size_t)r * O + o] = mn;
    }
    int slot = blockIdx.x * G + sub;
    g_ps1[(size_t)o * 4096 + slot] = ts1;
    g_ps2[(size_t)o * 4096 + slot] = ts2;
}

__global__ __launch_bounds__(256) void reduce_stats_kernel() {
    __shared__ float sh1[256], sh2[256];
    int o = blockIdx.x;
    int tid = threadIdx.x;
    const float* p1 = g_ps1 + (size_t)o * 4096;
    const float* p2 = g_ps2 + (size_t)o * 4096;
    float s1 = 0.f, s2 = 0.f;
    for (int t = 0; t < 16; t++) { s1 += p1[tid + 256 * t]; s2 += p2[tid + 256 * t]; }
    sh1[tid] = s1; sh2[tid] = s2;
    __syncthreads();
    for (int s = 128; s; s >>= 1) {
        if (tid < s) { sh1[tid] += sh1[tid + s]; sh2[tid] += sh2[tid + s]; }
        __syncthreads();
    }
    if (tid == 0) { g_s1[o] = sh1[0]; g_s2[o] = sh2[0]; }
}

// BN + LeakyReLU on pooled value; write fp32 result AND its bf16 hi/lo split (head operands)
__global__ void finalize_kernel(int O, int colbase,
                                const float* __restrict__ gamma,
                                const float* __restrict__ beta) {
    int id = blockIdx.x * 256 + threadIdx.x;
    int r = id / O, o = id - r * O;
    const float invCNT = 1.f / (float)(BATCH * NPTS * KNN);
    float mean = g_s1[o] * invCNT;
    float var = g_s2[o] * invCNT - mean * mean;
    float scale = gamma[o] * rsqrtf(var + EPSBN);
    float shift = beta[o] - mean * scale;
    float sel = (scale >= 0.f) ? g_mx[(size_t)r * O + o] : g_mn[(size_t)r * O + o];
    float v = fmaf(scale, sel, shift);
    float res = (v >= 0.f) ? v : 0.2f * v;
    size_t oidx = (size_t)r * 512 + colbase + o;
    g_xcat[oidx] = res;
    __nv_bfloat16 h = __float2bfloat16(res);
    g_xch[oidx] = h;
    g_xcl[oidx] = __float2bfloat16(res - __bfloat162float(h));
}

__global__ void init_final_kernel() {
    int id = blockIdx.x * blockDim.x + threadIdx.x;
    if (id < BATCH * 1024) { g_fmx[id] = -FLT_MAX; g_fmn[id] = FLT_MAX; }
}

__global__ void out_kernel(const float* __restrict__ g5, const float* __restrict__ b5,
                           float* __restrict__ out) {
    int id = blockIdx.x * blockDim.x + threadIdx.x;
    if (id >= BATCH * 1024) return;
    int o = id & 1023;
    const float invCNT = 1.f / (float)(BATCH * NPTS);
    float mean = g_fs1[o] * invCNT;
    float var = g_fs2[o] * invCNT - mean * mean;
    float scale = g5[o] * rsqrtf(var + EPSBN);
    float shift = b5[o] - mean * scale;
    float sel = (scale >= 0.f) ? g_fmx[id] : g_fmn[id];
    float v = fmaf(scale, sel, shift);
    out[id] = (v >= 0.f) ? v : 0.2f * v;
}

// ---------------- host driver ----------------

extern "C" void kernel_launch(void* const* d_in, const int* in_sizes, int n_in,
                              void* d_out, int out_size) {
    const float* x  = (const float*)d_in[0];
    const float* w1 = (const float*)d_in[1];
    const float* g1 = (const float*)d_in[2];
    const float* b1 = (const float*)d_in[3];
    const float* w2 = (const float*)d_in[4];
    const float* g2 = (const float*)d_in[5];
    const float* b2 = (const float*)d_in[6];
    const float* w3 = (const float*)d_in[7];
    const float* g3 = (const float*)d_in[8];
    const float* b3 = (const float*)d_in[9];
    const float* w4 = (const float*)d_in[10];
    const float* g4 = (const float*)d_in[11];
    const float* b4 = (const float*)d_in[12];
    const float* w5 = (const float*)d_in[13];
    const float* g5 = (const float*)d_in[14];
    const float* b5 = (const float*)d_in[15];

    transpose_in_kernel<<<(BATCH * 3 * NPTS + 255) / 256, 256>>>(x);
    split_w5_kernel<<<(1024 * 512) / 256, 256>>>(w5);

    dim3 gramGrid(136, 1, BATCH);

    // ---- layer 1: C=3, S=3, O=64 ----
    sq_kernel<<<(BATCH * NPTS) / 8, 256>>>(0, 0, 3, 3);
    gram1_kernel<<<dim3(NPTS / 32, BATCH), 256>>>();
    topk_kernel<<<BATCH * NPTS, 256>>>();
    wpack_kernel<<<(128 * 3 + 255) / 256, 256>>>(w1, 3, 64);
    pq_kernel<3, 3, 0, 128><<<dim3(NPTS / 128, 1, BATCH), 256>>>();
    gather_kernel<<<(BATCH * NPTS * 64) / 1024, 256>>>(64);
    reduce_stats_kernel<<<64, 256>>>();
    finalize_kernel<<<(BATCH * NPTS * 64) / 256, 256>>>(64, 0, g1, b1);

    // ---- layer 2: C=64, coloff=0, O=64 ----
    sq_kernel<<<(BATCH * NPTS) / 8, 256>>>(1, 0, 64, 512);
    gram_kernel<64, 512, 0><<<gramGrid, 256>>>();
    topk_kernel<<<BATCH * NPTS, 256>>>();
    wpack_kernel<<<(128 * 64 + 255) / 256, 256>>>(w2, 64, 64);
    pq_kernel<64, 512, 0, 128><<<dim3(NPTS / 128, 1, BATCH), 256>>>();
    gather_kernel<<<(BATCH * NPTS * 64) / 1024, 256>>>(64);
    reduce_stats_kernel<<<64, 256>>>();
    finalize_kernel<<<(BATCH * NPTS * 64) / 256, 256>>>(64, 64, g2, b2);

    // ---- layer 3: C=64, coloff=64, O=128 ----
    sq_kernel<<<(BATCH * NPTS) / 8, 256>>>(1, 64, 64, 512);
    gram_kernel<64, 512, 64><<<gramGrid, 256>>>();
    topk_kernel<<<BATCH * NPTS, 256>>>();
    wpack_kernel<<<(256 * 64 + 255) / 256, 256>>>(w3, 64, 128);
    pq_kernel<64, 512, 64, 256><<<dim3(NPTS / 128, 2, BATCH), 256>>>();
    gather_kernel<<<(BATCH * NPTS * 128) / 1024, 256>>>(128);
    reduce_stats_kernel<<<128, 256>>>();
    finalize_kernel<<<(BATCH * NPTS * 128) / 256, 256>>>(128, 128, g3, b3);

    // ---- layer 4: C=128, coloff=128, O=256 ----
    sq_kernel<<<(BATCH * NPTS) / 8, 256>>>(1, 128, 128, 512);
    gram_kernel<128, 512, 128><<<gramGrid, 256>>>();
    topk_kernel<<<BATCH * NPTS, 256>>>();
    wpack_kernel<<<(512 * 128 + 255) / 256, 256>>>(w4, 128, 256);
    pq_kernel<128, 512, 128, 512><<<dim3(NPTS / 128, 4, BATCH), 256>>>();
    gather_kernel<<<(BATCH * NPTS * 256) / 1024, 256>>>(256);
    reduce_stats_kernel<<<256, 256>>>();
    finalize_kernel<<<(BATCH * NPTS * 256) / 256, 256>>>(256, 256, g4, b4);

    // ---- head: bf16 double-split tensor-core GEMM ----
    init_final_kernel<<<32, 256>>>();
    head_mma_kernel<<<dim3(1024 / 128, NPTS / 128, BATCH), 256>>>();
    reduce_final_kernel<<<4, 256>>>();
    out_kernel<<<32, 256>>>(g5, b5, (float*)d_out);
}